// round 5
// baseline (speedup 1.0000x reference)
#include <cuda_runtime.h>
#include <cstdint>

// Submanifold 3x3 conv (cross-correlation, SAME) on independent 4x4x1 tiles.
// One thread per ROW-PAIR (2x float4 = 32B); tile = 2 adjacent lanes.
// Single butterfly exchange (shfl.xor 1) supplies the one partner row each
// lane needs. Both output rows computed together with packed fma.rn.f32x2
// (s0 in lo lane, s1 in hi lane). Weights live in __constant__ (uniform LDCU
// path; no smem, no barrier).

__constant__ float cW[9];

__device__ __forceinline__ unsigned long long pk2(float lo, float hi) {
    unsigned long long r;
    asm("mov.b64 %0, {%1, %2};" : "=l"(r) : "f"(lo), "f"(hi));
    return r;
}
__device__ __forceinline__ unsigned long long fma2(
    unsigned long long a, unsigned long long b, unsigned long long c) {
    unsigned long long d;
    asm("fma.rn.f32x2 %0, %1, %2, %3;" : "=l"(d) : "l"(a), "l"(b), "l"(c));
    return d;
}
__device__ __forceinline__ unsigned long long mul2(
    unsigned long long a, unsigned long long b) {
    unsigned long long d;
    asm("mul.rn.f32x2 %0, %1, %2;" : "=l"(d) : "l"(a), "l"(b));
    return d;
}
__device__ __forceinline__ void upk2(unsigned long long v, float& lo, float& hi) {
    asm("mov.b64 {%0, %1}, %2;" : "=f"(lo), "=f"(hi) : "l"(v));
}

__global__ __launch_bounds__(256) void subm_conv_pair_f32x2_kernel(
    const float4* __restrict__ x,
    float4* __restrict__ y,
    int n_pairs)
{
    int gid = blockIdx.x * blockDim.x + threadIdx.x;
    if (gid >= n_pairs) return;

    const float4* xin = x + 2 * (size_t)gid;
    float4 r0 = __ldcs(xin + 0);
    float4 r1 = __ldcs(xin + 1);
    bool top = ((gid & 1) == 0);

    // Butterfly exchange with partner lane (same tile).
    float4 send = top ? r1 : r0;
    float4 recv;
    recv.x = __shfl_xor_sync(0xffffffffu, send.x, 1);
    recv.y = __shfl_xor_sync(0xffffffffu, send.y, 1);
    recv.z = __shfl_xor_sync(0xffffffffu, send.z, 1);
    recv.w = __shfl_xor_sync(0xffffffffu, send.w, 1);

    float4 zero4 = make_float4(0.f, 0.f, 0.f, 0.f);
    float4 a = top ? zero4 : recv;   // row above r0
    float4 b = top ? recv : zero4;   // row below r1

    float ra[4] = {a.x,  a.y,  a.z,  a.w};
    float rm[4] = {r0.x, r0.y, r0.z, r0.w};
    float rn[4] = {r1.x, r1.y, r1.z, r1.w};
    float rb[4] = {b.x,  b.y,  b.z,  b.w};

    // Packed input rows: lane0 feeds output-row s0 (rows ra,rm,rn),
    // lane1 feeds output-row s1 (rows rm,rn,rb).
    unsigned long long P0[4], P1[4], P2[4];
#pragma unroll
    for (int c = 0; c < 4; c++) {
        P0[c] = pk2(ra[c], rm[c]);
        P1[c] = pk2(rm[c], rn[c]);
        P2[c] = pk2(rn[c], rb[c]);
    }

    // Broadcast-packed weights (from uniform constant regs).
    unsigned long long ww[9];
#pragma unroll
    for (int i = 0; i < 9; i++) ww[i] = pk2(cW[i], cW[i]);

    // S[j] = sum over weight rows k, weight cols c of Pk[j+c-1]*w[k][c],
    // taps with j+c-1 outside [0,3] are zero (dropped).
    unsigned long long S0, S1, S2, S3;
    // j = 0: taps t=0 (c=1), t=1 (c=2)
    S0 = mul2(P0[0], ww[1]);
    S0 = fma2(P1[0], ww[4], S0);
    S0 = fma2(P2[0], ww[7], S0);
    S0 = fma2(P0[1], ww[2], S0);
    S0 = fma2(P1[1], ww[5], S0);
    S0 = fma2(P2[1], ww[8], S0);
    // j = 1: t=0..2
    S1 = mul2(P0[0], ww[0]);
    S1 = fma2(P1[0], ww[3], S1);
    S1 = fma2(P2[0], ww[6], S1);
    S1 = fma2(P0[1], ww[1], S1);
    S1 = fma2(P1[1], ww[4], S1);
    S1 = fma2(P2[1], ww[7], S1);
    S1 = fma2(P0[2], ww[2], S1);
    S1 = fma2(P1[2], ww[5], S1);
    S1 = fma2(P2[2], ww[8], S1);
    // j = 2: t=1..3
    S2 = mul2(P0[1], ww[0]);
    S2 = fma2(P1[1], ww[3], S2);
    S2 = fma2(P2[1], ww[6], S2);
    S2 = fma2(P0[2], ww[1], S2);
    S2 = fma2(P1[2], ww[4], S2);
    S2 = fma2(P2[2], ww[7], S2);
    S2 = fma2(P0[3], ww[2], S2);
    S2 = fma2(P1[3], ww[5], S2);
    S2 = fma2(P2[3], ww[8], S2);
    // j = 3: taps t=2 (c=0), t=3 (c=1)
    S3 = mul2(P0[2], ww[0]);
    S3 = fma2(P1[2], ww[3], S3);
    S3 = fma2(P2[2], ww[6], S3);
    S3 = fma2(P0[3], ww[1], S3);
    S3 = fma2(P1[3], ww[4], S3);
    S3 = fma2(P2[3], ww[7], S3);

    float o0[4], o1[4];
    upk2(S0, o0[0], o1[0]);
    upk2(S1, o0[1], o1[1]);
    upk2(S2, o0[2], o1[2]);
    upk2(S3, o0[3], o1[3]);

    // Submanifold mask: write only at active (nonzero-input) sites.
#pragma unroll
    for (int j = 0; j < 4; j++) {
        o0[j] = (rm[j] != 0.0f) ? o0[j] : 0.0f;
        o1[j] = (rn[j] != 0.0f) ? o1[j] : 0.0f;
    }

    float4* yout = y + 2 * (size_t)gid;
    __stcs(yout + 0, make_float4(o0[0], o0[1], o0[2], o0[3]));
    __stcs(yout + 1, make_float4(o1[0], o1[1], o1[2], o1[3]));
}

extern "C" void kernel_launch(void* const* d_in, const int* in_sizes, int n_in,
                              void* d_out, int out_size)
{
    const float4* x = (const float4*)d_in[0];
    const float* W = (const float*)d_in[1];
    float4* y = (float4*)d_out;

    // Stage weights into constant memory (D2D async copy; graph-capturable).
    cudaMemcpyToSymbolAsync(cW, W, 9 * sizeof(float), 0,
                            cudaMemcpyDeviceToDevice, 0);

    int n_pairs = in_sizes[0] / 8;     // one thread per 8 floats (2 rows)
    int threads = 256;
    int blocks = (n_pairs + threads - 1) / threads;
    subm_conv_pair_f32x2_kernel<<<blocks, threads>>>(x, y, n_pairs);
}

// round 6
// speedup vs baseline: 1.0360x; 1.0360x over previous
#include <cuda_runtime.h>
#include <cstdint>

// Submanifold 3x3 conv (cross-correlation, SAME) on independent 4x4x1 tiles.
// One thread per ROW-PAIR (2x float4 = 32B); tile = 2 adjacent lanes.
// Single butterfly exchange (shfl.xor 1) supplies the one partner row each
// lane needs. Both output rows computed together with packed fma.rn.f32x2
// (row-s0 in lo half, row-s1 in hi half). Weights loaded in-kernel via 3
// broadcast __ldg loads (L1 hits; no smem, no barrier, no extra graph node).

__device__ __forceinline__ unsigned long long pk2(float lo, float hi) {
    unsigned long long r;
    asm("mov.b64 %0, {%1, %2};" : "=l"(r) : "f"(lo), "f"(hi));
    return r;
}
__device__ __forceinline__ unsigned long long fma2(
    unsigned long long a, unsigned long long b, unsigned long long c) {
    unsigned long long d;
    asm("fma.rn.f32x2 %0, %1, %2, %3;" : "=l"(d) : "l"(a), "l"(b), "l"(c));
    return d;
}
__device__ __forceinline__ unsigned long long mul2(
    unsigned long long a, unsigned long long b) {
    unsigned long long d;
    asm("mul.rn.f32x2 %0, %1, %2;" : "=l"(d) : "l"(a), "l"(b));
    return d;
}
__device__ __forceinline__ void upk2(unsigned long long v, float& lo, float& hi) {
    asm("mov.b64 {%0, %1}, %2;" : "=f"(lo), "=f"(hi) : "l"(v));
}

__global__ __launch_bounds__(256) void subm_conv_pair_f32x2_kernel(
    const float4* __restrict__ x,
    const float* __restrict__ W,
    float4* __restrict__ y,
    int n_pairs)
{
    int gid = blockIdx.x * blockDim.x + threadIdx.x;
    if (gid >= n_pairs) return;

    const float4* xin = x + 2 * (size_t)gid;
    float4 r0 = __ldcs(xin + 0);
    float4 r1 = __ldcs(xin + 1);
    bool top = ((gid & 1) == 0);

    // Broadcast weight loads (all lanes same address -> L1 broadcast hits).
    float4 w03 = __ldg(reinterpret_cast<const float4*>(W));
    float4 w47 = __ldg(reinterpret_cast<const float4*>(W) + 1);
    float  w8f = __ldg(W + 8);

    // Butterfly exchange with partner lane (same tile).
    float4 send = top ? r1 : r0;
    float4 recv;
    recv.x = __shfl_xor_sync(0xffffffffu, send.x, 1);
    recv.y = __shfl_xor_sync(0xffffffffu, send.y, 1);
    recv.z = __shfl_xor_sync(0xffffffffu, send.z, 1);
    recv.w = __shfl_xor_sync(0xffffffffu, send.w, 1);

    float4 zero4 = make_float4(0.f, 0.f, 0.f, 0.f);
    float4 a = top ? zero4 : recv;   // row above r0
    float4 b = top ? recv : zero4;   // row below r1

    float ra[4] = {a.x,  a.y,  a.z,  a.w};
    float rm[4] = {r0.x, r0.y, r0.z, r0.w};
    float rn[4] = {r1.x, r1.y, r1.z, r1.w};
    float rb[4] = {b.x,  b.y,  b.z,  b.w};

    // Packed input rows: lo half feeds output-row s0 (rows ra,rm,rn),
    // hi half feeds output-row s1 (rows rm,rn,rb).
    unsigned long long P0[4], P1[4], P2[4];
#pragma unroll
    for (int c = 0; c < 4; c++) {
        P0[c] = pk2(ra[c], rm[c]);
        P1[c] = pk2(rm[c], rn[c]);
        P2[c] = pk2(rn[c], rb[c]);
    }

    // Broadcast-packed weights.
    unsigned long long ww[9];
    ww[0] = pk2(w03.x, w03.x);
    ww[1] = pk2(w03.y, w03.y);
    ww[2] = pk2(w03.z, w03.z);
    ww[3] = pk2(w03.w, w03.w);
    ww[4] = pk2(w47.x, w47.x);
    ww[5] = pk2(w47.y, w47.y);
    ww[6] = pk2(w47.z, w47.z);
    ww[7] = pk2(w47.w, w47.w);
    ww[8] = pk2(w8f,  w8f);

    // S[j] = sum over weight rows k, cols c of Pk[j+c-1]*w[k][c]; taps with
    // j+c-1 outside [0,3] are zero (dropped).
    unsigned long long S0, S1, S2, S3;
    // j = 0
    S0 = mul2(P0[0], ww[1]);
    S0 = fma2(P1[0], ww[4], S0);
    S0 = fma2(P2[0], ww[7], S0);
    S0 = fma2(P0[1], ww[2], S0);
    S0 = fma2(P1[1], ww[5], S0);
    S0 = fma2(P2[1], ww[8], S0);
    // j = 1
    S1 = mul2(P0[0], ww[0]);
    S1 = fma2(P1[0], ww[3], S1);
    S1 = fma2(P2[0], ww[6], S1);
    S1 = fma2(P0[1], ww[1], S1);
    S1 = fma2(P1[1], ww[4], S1);
    S1 = fma2(P2[1], ww[7], S1);
    S1 = fma2(P0[2], ww[2], S1);
    S1 = fma2(P1[2], ww[5], S1);
    S1 = fma2(P2[2], ww[8], S1);
    // j = 2
    S2 = mul2(P0[1], ww[0]);
    S2 = fma2(P1[1], ww[3], S2);
    S2 = fma2(P2[1], ww[6], S2);
    S2 = fma2(P0[2], ww[1], S2);
    S2 = fma2(P1[2], ww[4], S2);
    S2 = fma2(P2[2], ww[7], S2);
    S2 = fma2(P0[3], ww[2], S2);
    S2 = fma2(P1[3], ww[5], S2);
    S2 = fma2(P2[3], ww[8], S2);
    // j = 3
    S3 = mul2(P0[2], ww[0]);
    S3 = fma2(P1[2], ww[3], S3);
    S3 = fma2(P2[2], ww[6], S3);
    S3 = fma2(P0[3], ww[1], S3);
    S3 = fma2(P1[3], ww[4], S3);
    S3 = fma2(P2[3], ww[7], S3);

    float o0[4], o1[4];
    upk2(S0, o0[0], o1[0]);
    upk2(S1, o0[1], o1[1]);
    upk2(S2, o0[2], o1[2]);
    upk2(S3, o0[3], o1[3]);

    // Submanifold mask: write only at active (nonzero-input) sites.
#pragma unroll
    for (int j = 0; j < 4; j++) {
        o0[j] = (rm[j] != 0.0f) ? o0[j] : 0.0f;
        o1[j] = (rn[j] != 0.0f) ? o1[j] : 0.0f;
    }

    float4* yout = y + 2 * (size_t)gid;
    __stcs(yout + 0, make_float4(o0[0], o0[1], o0[2], o0[3]));
    __stcs(yout + 1, make_float4(o1[0], o1[1], o1[2], o1[3]));
}

extern "C" void kernel_launch(void* const* d_in, const int* in_sizes, int n_in,
                              void* d_out, int out_size)
{
    const float4* x = (const float4*)d_in[0];
    const float* W = (const float*)d_in[1];
    float4* y = (float4*)d_out;

    int n_pairs = in_sizes[0] / 8;     // one thread per 8 floats (2 rows)
    int threads = 256;
    int blocks = (n_pairs + threads - 1) / threads;
    subm_conv_pair_f32x2_kernel<<<blocks, threads>>>(x, W, y, n_pairs);
}

// round 7
// speedup vs baseline: 1.0382x; 1.0022x over previous
#include <cuda_runtime.h>
#include <cstdint>

// Submanifold 3x3 conv (cross-correlation, SAME) on independent 4x4x1 tiles.
// One thread per ROW-PAIR (2x float4 = 32B); tile = 2 adjacent threads.
// No shuffles: the one extra row each thread needs is loaded directly with a
// predicated LDG from the neighboring float4 (its cache line is already being
// fetched by the warp, so it's an L1 sector hit; DRAM traffic unchanged).
// Both output rows are computed together with packed fma.rn.f32x2.

__device__ __forceinline__ unsigned long long pk2(float lo, float hi) {
    unsigned long long r;
    asm("mov.b64 %0, {%1, %2};" : "=l"(r) : "f"(lo), "f"(hi));
    return r;
}
__device__ __forceinline__ unsigned long long fma2(
    unsigned long long a, unsigned long long b, unsigned long long c) {
    unsigned long long d;
    asm("fma.rn.f32x2 %0, %1, %2, %3;" : "=l"(d) : "l"(a), "l"(b), "l"(c));
    return d;
}
__device__ __forceinline__ unsigned long long mul2(
    unsigned long long a, unsigned long long b) {
    unsigned long long d;
    asm("mul.rn.f32x2 %0, %1, %2;" : "=l"(d) : "l"(a), "l"(b));
    return d;
}
__device__ __forceinline__ void upk2(unsigned long long v, float& lo, float& hi) {
    asm("mov.b64 {%0, %1}, %2;" : "=f"(lo), "=f"(hi) : "l"(v));
}

__global__ __launch_bounds__(256) void subm_conv_pair_noshfl_kernel(
    const float4* __restrict__ x,
    const float* __restrict__ W,
    float4* __restrict__ y,
    int n_pairs)
{
    int gid = blockIdx.x * blockDim.x + threadIdx.x;
    if (gid >= n_pairs) return;

    bool hi_half = (gid & 1) != 0;   // p=1: rows 2,3 of the tile
    const float4* base = x + 2 * (size_t)gid;

    // My two rows.
    float4 m = __ldcs(base + 0);
    float4 n = __ldcs(base + 1);

    // Neighbor row within the tile (predicated load; edge row stays zero).
    float4 a = make_float4(0.f, 0.f, 0.f, 0.f);  // row above m
    float4 b = make_float4(0.f, 0.f, 0.f, 0.f);  // row below n
    if (hi_half) a = __ldcs(base - 1);
    else         b = __ldcs(base + 2);

    // Broadcast weight loads (uniform address -> L1 broadcast hits).
    float4 w03 = __ldg(reinterpret_cast<const float4*>(W));
    float4 w47 = __ldg(reinterpret_cast<const float4*>(W) + 1);
    float  w8f = __ldg(W + 8);

    float ra[4] = {a.x, a.y, a.z, a.w};
    float rm[4] = {m.x, m.y, m.z, m.w};
    float rn[4] = {n.x, n.y, n.z, n.w};
    float rb[4] = {b.x, b.y, b.z, b.w};

    // Packed input rows: lo half feeds output-row m (rows ra,rm,rn),
    // hi half feeds output-row n (rows rm,rn,rb).
    unsigned long long P0[4], P1[4], P2[4];
#pragma unroll
    for (int c = 0; c < 4; c++) {
        P0[c] = pk2(ra[c], rm[c]);
        P1[c] = pk2(rm[c], rn[c]);
        P2[c] = pk2(rn[c], rb[c]);
    }

    unsigned long long ww[9];
    ww[0] = pk2(w03.x, w03.x);
    ww[1] = pk2(w03.y, w03.y);
    ww[2] = pk2(w03.z, w03.z);
    ww[3] = pk2(w03.w, w03.w);
    ww[4] = pk2(w47.x, w47.x);
    ww[5] = pk2(w47.y, w47.y);
    ww[6] = pk2(w47.z, w47.z);
    ww[7] = pk2(w47.w, w47.w);
    ww[8] = pk2(w8f,  w8f);

    // S[j] = sum over weight rows k, cols c of Pk[j+c-1]*w[k][c]; taps with
    // j+c-1 outside [0,3] are zero (dropped).
    unsigned long long S0, S1, S2, S3;
    // j = 0
    S0 = mul2(P0[0], ww[1]);
    S0 = fma2(P1[0], ww[4], S0);
    S0 = fma2(P2[0], ww[7], S0);
    S0 = fma2(P0[1], ww[2], S0);
    S0 = fma2(P1[1], ww[5], S0);
    S0 = fma2(P2[1], ww[8], S0);
    // j = 1
    S1 = mul2(P0[0], ww[0]);
    S1 = fma2(P1[0], ww[3], S1);
    S1 = fma2(P2[0], ww[6], S1);
    S1 = fma2(P0[1], ww[1], S1);
    S1 = fma2(P1[1], ww[4], S1);
    S1 = fma2(P2[1], ww[7], S1);
    S1 = fma2(P0[2], ww[2], S1);
    S1 = fma2(P1[2], ww[5], S1);
    S1 = fma2(P2[2], ww[8], S1);
    // j = 2
    S2 = mul2(P0[1], ww[0]);
    S2 = fma2(P1[1], ww[3], S2);
    S2 = fma2(P2[1], ww[6], S2);
    S2 = fma2(P0[2], ww[1], S2);
    S2 = fma2(P1[2], ww[4], S2);
    S2 = fma2(P2[2], ww[7], S2);
    S2 = fma2(P0[3], ww[2], S2);
    S2 = fma2(P1[3], ww[5], S2);
    S2 = fma2(P2[3], ww[8], S2);
    // j = 3
    S3 = mul2(P0[2], ww[0]);
    S3 = fma2(P1[2], ww[3], S3);
    S3 = fma2(P2[2], ww[6], S3);
    S3 = fma2(P0[3], ww[1], S3);
    S3 = fma2(P1[3], ww[4], S3);
    S3 = fma2(P2[3], ww[7], S3);

    float o0[4], o1[4];
    upk2(S0, o0[0], o1[0]);
    upk2(S1, o0[1], o1[1]);
    upk2(S2, o0[2], o1[2]);
    upk2(S3, o0[3], o1[3]);

    // Submanifold mask: write only at active (nonzero-input) sites.
#pragma unroll
    for (int j = 0; j < 4; j++) {
        o0[j] = (rm[j] != 0.0f) ? o0[j] : 0.0f;
        o1[j] = (rn[j] != 0.0f) ? o1[j] : 0.0f;
    }

    float4* yout = y + 2 * (size_t)gid;
    __stcs(yout + 0, make_float4(o0[0], o0[1], o0[2], o0[3]));
    __stcs(yout + 1, make_float4(o1[0], o1[1], o1[2], o1[3]));
}

extern "C" void kernel_launch(void* const* d_in, const int* in_sizes, int n_in,
                              void* d_out, int out_size)
{
    const float4* x = (const float4*)d_in[0];
    const float* W = (const float*)d_in[1];
    float4* y = (float4*)d_out;

    int n_pairs = in_sizes[0] / 8;     // one thread per 8 floats (2 rows)
    int threads = 256;
    int blocks = (n_pairs + threads - 1) / threads;
    subm_conv_pair_noshfl_kernel<<<blocks, threads>>>(x, W, y, n_pairs);
}